// round 6
// baseline (speedup 1.0000x reference)
#include <cuda_runtime.h>
#include <cuda_bf16.h>
#include <cstdint>

// Problem constants: N=512, B=256, F=400, D=14, K=2
#define GS_B 256
#define GS_F 400
#define GS_BF (GS_B * GS_F)      // 102400
#define GS_D 14
#define GS_DD (GS_D * GS_D)      // 196
#define GS_K 2

#define BFS 32                    // images per block
#define NT (BFS * GS_D)           // 448 threads
#define OUT_BYTES (BFS * GS_DD * 4)   // 25088 bytes per block

typedef unsigned long long ull;

__device__ __forceinline__ float ex2f(float x) {
    float y;
    asm("ex2.approx.f32 %0, %1;" : "=f"(y) : "f"(x));
    return y;
}

#define PACK2(d, lo, hi) \
    asm("mov.b64 %0, {%1, %2};" : "=l"(d) : "f"(lo), "f"(hi))
#define MUL2(d, a, b) \
    asm("mul.rn.f32x2 %0, %1, %2;" : "=l"(d) : "l"(a), "l"(b))
#define ADD2(d, a, b) \
    asm("add.rn.f32x2 %0, %1, %2;" : "=l"(d) : "l"(a), "l"(b))

__global__ __launch_bounds__(NT) void gs_fused(
    const int*          __restrict__ batch_idx,   // (B,)
    const unsigned int* __restrict__ m_mask,      // (B,F,K)
    const float*        __restrict__ height,      // (B,F,K)
    const float*        __restrict__ width,       // (B,F,K)
    const float*        __restrict__ x0,          // (B,F,K)
    const float*        __restrict__ y0,          // (B,F,K)
    const float*        __restrict__ background,  // (B,F)
    const float*        __restrict__ target_locs, // (N,F,2)
    float*              __restrict__ out)         // (B,F,D,D)
{
    __shared__ __align__(16) float sparams[BFS][16];   // 2 KB param table
    __shared__ __align__(16) float sbuf[NT * GS_D];    // 24.5 KB staging

    const int t    = threadIdx.x;
    const int wid  = t >> 5;
    const int lane = t & 31;

    // ---- Phase A: 64 (bfl,k) digests, 5 lanes per warp (14 warps) ----
    const int pidx = wid * 5 + lane;
    if (lane < 5 && pidx < 2 * BFS) {
        const int bfl = pidx >> 1;
        const int k   = pidx & 1;
        const int bf  = blockIdx.x * BFS + bfl;
        const int b   = bf / GS_F;
        const int f   = bf - b * GS_F;

        const int   bi  = __ldg(&batch_idx[b]);
        const int   tlo = (bi * GS_F + f) * 2;
        const float tlx = __ldg(&target_locs[tlo]);
        const float tly = __ldg(&target_locs[tlo + 1]);

        const int i = bf * GS_K + k;
        const unsigned int m = __ldg(&m_mask[i]);
        const float h  = (m != 0u) ? __ldg(&height[i]) : 0.0f;
        const float w  = __ldg(&width[i]);
        const float invw2 = __fdividef(1.0f, w * w);

        const float HALF_LOG2E = 0.7213475204444817f;   // 0.5*log2(e)
        const float INV_2PI    = 0.15915494309189535f;

        const float aL  = -HALF_LOG2E * invw2;           // log2-domain scale
        const float l2c = __log2f(h * INV_2PI * invw2);  // h==0 -> -inf -> e==0
        const float sx  = tlx + __ldg(&x0[i]);
        const float sy  = tly + __ldg(&y0[i]);

        const float base2 = fmaf(aL * sy, sy, l2c);
        const float v0 = ex2f(aL * (1.0f - 2.0f * sy));
        const float V  = ex2f(2.0f * aL);
        const float v1 = v0 * V;
        const float v2 = v1 * V;
        const float V2 = V * V;
        const float bgv = (k == 0) ? __ldg(&background[bf]) : 0.0f;

        float4* row = reinterpret_cast<float4*>(&sparams[bfl][8 * k]);
        row[0] = make_float4(sx, aL, base2, v0);
        row[1] = make_float4(v0 * v1, v1 * v2, V2 * V2, bgv);
    }
    __syncthreads();

    // ---- Phase B: packed f32x2 row recurrence (14 pixels / thread) ----
    const int bfl = t / GS_D;
    const int px  = t - bfl * GS_D;
    const float4* pp = reinterpret_cast<const float4*>(sparams[bfl]);
    const float4 p0 = pp[0];
    const float4 p1 = pp[1];
    const float4 p2 = pp[2];
    const float4 p3 = pp[3];

    const float fpx = (float)px;

    ull A[7];
    ull bgp; PACK2(bgp, p1.w, p1.w);

    // spot 0
    {
        const float dx = fpx - p0.x;
        const float e0 = ex2f(fmaf(p0.y * dx, dx, p0.z));
        const float e1 = e0 * p0.w;
        ull E; PACK2(E, e0, e1);
        ull P; PACK2(P, p1.x, p1.y);
        ull Vp; PACK2(Vp, p1.z, p1.z);
#pragma unroll
        for (int j = 0; j < 7; ++j) {
            ADD2(A[j], bgp, E);
            if (j < 6) { MUL2(E, E, P); MUL2(P, P, Vp); }
        }
    }
    // spot 1
    {
        const float dx = fpx - p2.x;
        const float e0 = ex2f(fmaf(p2.y * dx, dx, p2.z));
        const float e1 = e0 * p2.w;
        ull E; PACK2(E, e0, e1);
        ull P; PACK2(P, p3.x, p3.y);
        ull Vp; PACK2(Vp, p3.z, p3.z);
#pragma unroll
        for (int j = 0; j < 7; ++j) {
            ADD2(A[j], A[j], E);
            if (j < 6) { MUL2(E, E, P); MUL2(P, P, Vp); }
        }
    }

    // stage row into smem (row start = t*56 bytes, 8B aligned)
    ull* sp = reinterpret_cast<ull*>(&sbuf[t * GS_D]);
#pragma unroll
    for (int j = 0; j < 7; ++j) sp[j] = A[j];

    __syncthreads();

    // ---- writeout: one TMA bulk copy smem -> gmem (25088 B, contiguous) ----
    if (t == 0) {
        unsigned int saddr;
        asm("{ .reg .u64 tmp; cvta.to.shared.u64 tmp, %1; cvt.u32.u64 %0, tmp; }"
            : "=r"(saddr) : "l"(sbuf));
        float* gdst = out + (size_t)blockIdx.x * (BFS * GS_DD);
        asm volatile("fence.proxy.async.shared::cta;" ::: "memory");
        asm volatile("cp.async.bulk.global.shared::cta.bulk_group [%0], [%1], %2;"
                     :: "l"(gdst), "r"(saddr), "n"(OUT_BYTES) : "memory");
        asm volatile("cp.async.bulk.commit_group;" ::: "memory");
        asm volatile("cp.async.bulk.wait_group.read 0;" ::: "memory");
    }
}

extern "C" void kernel_launch(void* const* d_in, const int* in_sizes, int n_in,
                              void* d_out, int out_size) {
    const int*          batch_idx   = (const int*)d_in[0];
    const unsigned int* m_mask      = (const unsigned int*)d_in[1];
    const float*        height      = (const float*)d_in[2];
    const float*        width       = (const float*)d_in[3];
    const float*        x0          = (const float*)d_in[4];
    const float*        y0          = (const float*)d_in[5];
    const float*        background  = (const float*)d_in[6];
    const float*        target_locs = (const float*)d_in[7];
    // d_in[8] = pixel_pos: integer grid, regenerated analytically

    float* out = (float*)d_out;

    gs_fused<<<GS_BF / BFS, NT>>>(batch_idx, m_mask, height, width,
                                  x0, y0, background, target_locs, out);
}